// round 13
// baseline (speedup 1.0000x reference)
#include <cuda_runtime.h>

// VanillaRNN fused persistent kernel, v11: cols-per-thread 4 -> 8 to HALVE
// smem crossbar traffic (the co-limiter with the FMA pipe).
// B=1024, T=512, I=64, H=128, O=10.
// Grid: 128 CTAs x 8 rows (two 4-row groups, processed sequentially to bound
// register liveness), 256 threads, 1 CTA/SM (__launch_bounds__(256,1) for the
// full register budget; both groups share the 96 weight regs).
//
// Thread mapping: g = warp*2 + (lane&1) in [0,16): column group owning 8 cols
// {g + 16*cperm[c]}; seg = lane>>1 in [0,16): 12-wide k-segment of the
// 192-wide concat(x_t, h_t). Per thread per step: 24 LDS.128 (was 48),
// 384 FFMA2 (unchanged), 60 shuffles (was 28).
//
// Select-free 4-stage butterfly (all stages pure keep + shfl_xor(send)):
//   xor2 (sb0): rows 4->2   xor4 (sb1): rows 2->1
//   xor8 (sb2): cols 8->4   xor16 (sb3): cols 4->2
// via per-thread row order rKA/rSA/rKB/rSB (sb0,sb1) and col permutation
// cperm[j2j1j0] = 4*(j2?1-sb2:sb2) + 2*(j1?1-sb3:sb3) + j0.
// Lane finalizes row mstar = 2*sb0+sb1, cols {g+16*cperm[0], g+16*cperm[1]}.
//
// smem: buf[group][pingpong][row][320]; segment stride 20 floats (80 B:
// 16B-aligned bases, <=2-way bank overlap). One __syncthreads per step.
// tanh via MUFU tanh.approx.f32.

#define ROWS 4          // rows per group
#define NGROUPS 2
#define NTHREADS 256
#define HDIM 128
#define IDIM 64
#define TSTEPS 512
#define ODIM 10
#define SEGF 12
#define SEGP 20
#define RSTRIDE 320     // 16*20
#define GRID 128

__device__ __forceinline__ unsigned long long ffma2(unsigned long long a,
                                                    unsigned long long b,
                                                    unsigned long long c) {
    unsigned long long d;
    asm("fma.rn.f32x2 %0, %1, %2, %3;" : "=l"(d) : "l"(a), "l"(b), "l"(c));
    return d;
}

__device__ __forceinline__ unsigned long long packf2(float lo, float hi) {
    return ((unsigned long long)__float_as_uint(hi) << 32) |
           (unsigned long long)__float_as_uint(lo);
}

__device__ __forceinline__ float sum2(unsigned long long a) {
    return __uint_as_float((unsigned)a) + __uint_as_float((unsigned)(a >> 32));
}

__device__ __forceinline__ float tanh_fast(float z) {
    float r;
    asm("tanh.approx.f32 %0, %1;" : "=f"(r) : "f"(z));
    return r;
}

__device__ __forceinline__ int physk(int k) { return k + 8 * (k / SEGF); }

__device__ __forceinline__ float wpick(const float* __restrict__ W_hx,
                                       const float* __restrict__ W_hh,
                                       int o, int k) {
    return (k < IDIM) ? W_hx[o * IDIM + k] : W_hh[o * HDIM + (k - IDIM)];
}

// one row's 12-k slice (3 LDS.128) x 8 permuted cols = 48 FFMA2
__device__ __forceinline__ void row_acc8(const float* __restrict__ rowseg,
                                         const unsigned long long w[8][6],
                                         float sv[8]) {
    const ulonglong2* pp = (const ulonglong2*)rowseg;
    ulonglong2 v0 = pp[0], v1 = pp[1], v2 = pp[2];
    unsigned long long a[8];
#pragma unroll
    for (int c = 0; c < 8; c++) a[c] = ffma2(v0.x, w[c][0], 0ull);
#pragma unroll
    for (int c = 0; c < 8; c++) a[c] = ffma2(v0.y, w[c][1], a[c]);
#pragma unroll
    for (int c = 0; c < 8; c++) a[c] = ffma2(v1.x, w[c][2], a[c]);
#pragma unroll
    for (int c = 0; c < 8; c++) a[c] = ffma2(v1.y, w[c][3], a[c]);
#pragma unroll
    for (int c = 0; c < 8; c++) a[c] = ffma2(v2.x, w[c][4], a[c]);
#pragma unroll
    for (int c = 0; c < 8; c++) a[c] = ffma2(v2.y, w[c][5], a[c]);
#pragma unroll
    for (int c = 0; c < 8; c++) sv[c] = sum2(a[c]);
}

__global__ void __launch_bounds__(NTHREADS, 1)
rnn_fused_kernel(const float* __restrict__ x,
                 const float* __restrict__ W_hx,
                 const float* __restrict__ W_hh,
                 const float* __restrict__ b_hh,
                 const float* __restrict__ W_ph,
                 const float* __restrict__ b_ph,
                 float* __restrict__ out) {
    // buf[group][pingpong][row][phys-k]
    __shared__ __align__(16) float buf[NGROUPS][2][ROWS][RSTRIDE];

    const int tid  = threadIdx.x;
    const int lane = tid & 31;
    const int warp = tid >> 5;
    const int g    = warp * 2 + (lane & 1);   // col group 0..15
    const int seg  = lane >> 1;               // k-segment 0..15
    const int kb   = seg * SEGF;
    const int b0r  = blockIdx.x * (ROWS * NGROUPS);

    const int sb0 = seg & 1, sb1 = (seg >> 1) & 1,
              sb2 = (seg >> 2) & 1, sb3 = (seg >> 3) & 1;

    // per-thread permuted column order (stage-2/3 select elimination)
    int cperm[8];
#pragma unroll
    for (int j = 0; j < 8; j++) {
        const int j0 = j & 1, j1 = (j >> 1) & 1, j2 = (j >> 2) & 1;
        cperm[j] = 4 * (j2 ? (1 - sb2) : sb2) + 2 * (j1 ? (1 - sb3) : sb3) + j0;
    }

    // ---- weights in permuted col order: 8 x 6 packed f32x2 = 96 regs,
    // shared by both groups
    unsigned long long w[8][6];
#pragma unroll
    for (int c = 0; c < 8; c++) {
        const int o = g + 16 * cperm[c];
#pragma unroll
        for (int j = 0; j < 6; j++) {
            const int k0 = kb + 2 * j;
            w[c][j] = packf2(wpick(W_hx, W_hh, o, k0),
                             wpick(W_hx, W_hh, o, k0 + 1));
        }
    }

    // per-thread row order (stage-0/1 select elimination)
    const int rKA = sb1 + 2 * sb0;
    const int rSA = sb1 + 2 * (1 - sb0);
    const int rKB = (1 - sb1) + 2 * sb0;
    const int rSB = (1 - sb1) + 2 * (1 - sb0);
    const int segoff = seg * SEGP;
    const int oKA = rKA * RSTRIDE + segoff;
    const int oSA = rSA * RSTRIDE + segoff;
    const int oKB = rKB * RSTRIDE + segoff;
    const int oSB = rSB * RSTRIDE + segoff;

    const int mstar = 2 * sb0 + sb1;          // row this lane finalizes
    const int of0 = g + 16 * cperm[0];        // final two cols (cperm[1]=cperm[0]+1)
    const int of1 = of0 + 16;
    const float bb0 = b_hh[of0];
    const float bb1 = b_hh[of1];
    const int ph0 = physk(IDIM + of0);
    const int ph1 = physk(IDIM + of1);

    // ---- zero all buffers (h0 = 0)
    for (int i = tid; i < NGROUPS * 2 * ROWS * RSTRIDE; i += NTHREADS)
        ((float*)buf)[i] = 0.0f;

    // ---- x loader: tid<128 -> row xr = tid>>4 (0..7), float4 chunk c4.
    // 12 % 4 == 0 so chunks never straddle a segment.
    const int xr   = tid >> 4;
    const int xgrp = (xr >> 2) & 1;
    const int xrl  = xr & 3;
    const int c4   = (tid & 15) * 4;
    const int pc4  = physk(c4);
    const bool loader = (tid < 128);
    const float* xrow = x + (size_t)(b0r + (xr & 7)) * TSTEPS * IDIM;

    if (loader)
        *(float4*)&buf[xgrp][0][xrl][pc4] = *(const float4*)(xrow + c4);
    __syncthreads();

    int p = 0;
    for (int t = 0; t < TSTEPS; t++) {
        float4 xn;
        if (loader) {
            const int tn = (t + 1 < TSTEPS) ? t + 1 : TSTEPS - 1;
            xn = *(const float4*)(xrow + (size_t)tn * IDIM + c4);
        }

        const int q = p ^ 1;

        // ---- groups processed sequentially (register reuse); ptxas hoists
        // loads across as it sees fit.
#pragma unroll
        for (int grp = 0; grp < NGROUPS; grp++) {
            const float* base = &buf[grp][p][0][0];

            float aK[8], aS[8], ra[8];
            row_acc8(base + oKA, w, aK);
            row_acc8(base + oSA, w, aS);
#pragma unroll
            for (int c = 0; c < 8; c++)
                ra[c] = aK[c] + __shfl_xor_sync(0xffffffffu, aS[c], 2);

            float rb[8];
            row_acc8(base + oKB, w, aK);
            row_acc8(base + oSB, w, aS);
#pragma unroll
            for (int c = 0; c < 8; c++)
                rb[c] = aK[c] + __shfl_xor_sync(0xffffffffu, aS[c], 2);

            // stage 1 (xor 4): rows 2 -> 1
            float rc[8];
#pragma unroll
            for (int c = 0; c < 8; c++)
                rc[c] = ra[c] + __shfl_xor_sync(0xffffffffu, rb[c], 4);

            // stage 2 (xor 8): cols 8 -> 4
            float rd[4];
#pragma unroll
            for (int c = 0; c < 4; c++)
                rd[c] = rc[c] + __shfl_xor_sync(0xffffffffu, rc[c + 4], 8);

            // stage 3 (xor 16): cols 4 -> 2
            const float f0 = rd[0] + __shfl_xor_sync(0xffffffffu, rd[2], 16);
            const float f1 = rd[1] + __shfl_xor_sync(0xffffffffu, rd[3], 16);

            buf[grp][q][mstar][ph0] = tanh_fast(f0 + bb0);
            buf[grp][q][mstar][ph1] = tanh_fast(f1 + bb1);
        }

        if (loader) *(float4*)&buf[xgrp][q][xrl][pc4] = xn;

        __syncthreads();
        p = q;
    }

    // ---- final projection over all 8 rows
    if (tid < ROWS * NGROUPS * ODIM) {
        const int m = tid / ODIM;             // 0..7
        const int j = tid % ODIM;
        const int mg = m >> 2, mr = m & 3;
        float s = b_ph[j];
#pragma unroll 4
        for (int k = 0; k < HDIM; k++)
            s += buf[mg][p][mr][physk(IDIM + k)] * W_ph[j * HDIM + k];
        out[(size_t)(b0r + m) * ODIM + j] = s;
    }
}

extern "C" void kernel_launch(void* const* d_in, const int* in_sizes, int n_in,
                              void* d_out, int out_size) {
    const float* x    = (const float*)d_in[0];
    const float* W_hx = (const float*)d_in[1];
    const float* W_hh = (const float*)d_in[2];
    const float* b_hh = (const float*)d_in[3];
    const float* W_ph = (const float*)d_in[4];
    const float* b_ph = (const float*)d_in[5];
    float* out = (float*)d_out;

    rnn_fused_kernel<<<GRID, NTHREADS>>>(x, W_hx, W_hh, b_hh, W_ph, b_ph, out);
}

// round 14
// speedup vs baseline: 1.0891x; 1.0891x over previous
#include <cuda_runtime.h>

// VanillaRNN fused persistent kernel, v12 = v8 engine x2 with SPLIT NAMED
// BARRIERS for deterministic anti-phase MIO/FMA overlap.
// B=1024, T=512, I=64, H=128, O=10.
// Grid: 128 CTAs x 8 rows. Block: 512 threads = TWO 256-thread groups, each
// an independent v8-style engine for 4 batch rows with its OWN named barrier
// (bar.sync 1,256 / bar.sync 2,256). Group 1 runs a one-time ~500-cyc
// dependent-FMA stagger, so group A's LDS/shuffle (MIO) phase overlaps group
// B's FFMA phase every step -- breaking the chip-wide phase lock that made
// step = fma-busy + MIO-busy (serialized) in v8-v11.
//
// Per-group thread mapping (v8, select-free): g = warp*4 + (lane&3): column
// group, cols {g+32*cg[c]}; seg = lane>>2 in [0,8): 24-wide k-segment of the
// 192-wide concat(x_t, h_t). Butterfly xor4/xor8/xor16 as pure
// keep + shfl_xor(send) via per-thread row/col permutation.
// tanh via MUFU tanh.approx.f32. Segment stride 28 floats (conflict-free
// LDS.128). Double-buffered state; one named barrier per group per step.

#define ROWS 4          // rows per group
#define NGROUPS 2
#define NTHREADS 512
#define GTHREADS 256
#define HDIM 128
#define IDIM 64
#define TSTEPS 512
#define ODIM 10
#define SEGF 24
#define SEGP 28
#define RSTRIDE 228
#define GRID 128

__device__ __forceinline__ unsigned long long ffma2(unsigned long long a,
                                                    unsigned long long b,
                                                    unsigned long long c) {
    unsigned long long d;
    asm("fma.rn.f32x2 %0, %1, %2, %3;" : "=l"(d) : "l"(a), "l"(b), "l"(c));
    return d;
}

__device__ __forceinline__ unsigned long long packf2(float lo, float hi) {
    return ((unsigned long long)__float_as_uint(hi) << 32) |
           (unsigned long long)__float_as_uint(lo);
}

__device__ __forceinline__ float sum2(unsigned long long a) {
    return __uint_as_float((unsigned)a) + __uint_as_float((unsigned)(a >> 32));
}

__device__ __forceinline__ float tanh_fast(float z) {
    float r;
    asm("tanh.approx.f32 %0, %1;" : "=f"(r) : "f"(z));
    return r;
}

__device__ __forceinline__ void group_bar(int gid) {
    asm volatile("bar.sync %0, %1;" :: "r"(gid + 1), "n"(GTHREADS) : "memory");
}

__device__ __forceinline__ int physk(int k) { return k + 4 * (k / SEGF); }

__device__ __forceinline__ float wpick(const float* __restrict__ W_hx,
                                       const float* __restrict__ W_hh,
                                       int o, int k) {
    return (k < IDIM) ? W_hx[o * IDIM + k] : W_hh[o * HDIM + (k - IDIM)];
}

// accumulate one row's 24-k segment for this thread's 4 (permuted) cols
__device__ __forceinline__ void row_acc(const float* __restrict__ rowseg,
                                        const unsigned long long w[4][12],
                                        float sv[4]) {
    const ulonglong2* pp = (const ulonglong2*)rowseg;
    unsigned long long a0 = 0ull, a1 = 0ull, a2 = 0ull, a3 = 0ull;
#pragma unroll
    for (int i = 0; i < 6; i++) {
        ulonglong2 v = pp[i];
        a0 = ffma2(v.x, w[0][2 * i], a0);
        a1 = ffma2(v.x, w[1][2 * i], a1);
        a2 = ffma2(v.x, w[2][2 * i], a2);
        a3 = ffma2(v.x, w[3][2 * i], a3);
        a0 = ffma2(v.y, w[0][2 * i + 1], a0);
        a1 = ffma2(v.y, w[1][2 * i + 1], a1);
        a2 = ffma2(v.y, w[2][2 * i + 1], a2);
        a3 = ffma2(v.y, w[3][2 * i + 1], a3);
    }
    sv[0] = sum2(a0); sv[1] = sum2(a1); sv[2] = sum2(a2); sv[3] = sum2(a3);
}

__global__ void __launch_bounds__(NTHREADS, 1)
rnn_fused_kernel(const float* __restrict__ x,
                 const float* __restrict__ W_hx,
                 const float* __restrict__ W_hh,
                 const float* __restrict__ b_hh,
                 const float* __restrict__ W_ph,
                 const float* __restrict__ b_ph,
                 float* __restrict__ out) {
    // buf[group][pingpong][row][phys-k]
    __shared__ __align__(16) float buf[NGROUPS][2][ROWS][RSTRIDE];

    const int tid  = threadIdx.x;
    const int gid  = tid >> 8;            // group 0 or 1
    const int tg   = tid & 255;           // group-local tid
    const int lane = tg & 31;
    const int warp = tg >> 5;
    const int g    = warp * 4 + (lane & 3);   // col group 0..31
    const int seg  = lane >> 2;               // k-segment 0..7
    const int kb   = seg * SEGF;
    const int b0r  = blockIdx.x * (ROWS * NGROUPS) + gid * ROWS;

    const int sb0 = seg & 1, sb1 = (seg >> 1) & 1, sb2 = (seg >> 2) & 1;

    // per-thread permuted column order (stage-2 select elimination)
    int cg[4];
    cg[0] = 2 * sb2; cg[1] = 2 * sb2 + 1;
    cg[2] = 2 * (1 - sb2); cg[3] = 2 * (1 - sb2) + 1;

    // ---- weights in permuted col order: 48 ULL = 96 regs
    unsigned long long w[4][12];
#pragma unroll
    for (int c = 0; c < 4; c++) {
        const int o = g + 32 * cg[c];
#pragma unroll
        for (int j = 0; j < 12; j++) {
            const int k0 = kb + 2 * j;
            w[c][j] = packf2(wpick(W_hx, W_hh, o, k0),
                             wpick(W_hx, W_hh, o, k0 + 1));
        }
    }

    // per-thread row order (stage-0/1 select elimination)
    const int rKA = sb1 + 2 * sb0;
    const int rSA = sb1 + 2 * (1 - sb0);
    const int rKB = (1 - sb1) + 2 * sb0;
    const int rSB = (1 - sb1) + 2 * (1 - sb0);
    const int segoff = seg * SEGP;
    const int oKA = rKA * RSTRIDE + segoff;
    const int oSA = rSA * RSTRIDE + segoff;
    const int oKB = rKB * RSTRIDE + segoff;
    const int oSB = rSB * RSTRIDE + segoff;

    const int mstar = 2 * sb0 + sb1;          // row this lane finalizes
    const int of0 = g + 32 * cg[0];
    const int of1 = g + 32 * cg[1];
    const float bb0 = b_hh[of0];
    const float bb1 = b_hh[of1];
    const int ph0 = physk(IDIM + of0);
    const int ph1 = physk(IDIM + of1);

    // ---- zero all buffers (h0 = 0), whole CTA, then full sync ONCE
    for (int i = tid; i < NGROUPS * 2 * ROWS * RSTRIDE; i += NTHREADS)
        ((float*)buf)[i] = 0.0f;

    // ---- x loader (per group): tg<64, row xr, float4 chunk c4
    const int xr  = (tg >> 4) & 3;
    const int c4  = (tg & 15) * 4;
    const int pc4 = c4 + 4 * (c4 / SEGF);
    const bool loader = (tg < 64);
    const float* xrow = x + (size_t)(b0r + xr) * TSTEPS * IDIM;

    if (loader)
        *(float4*)&buf[gid][0][xr][pc4] = *(const float4*)(xrow + c4);
    __syncthreads();   // last CTA-wide barrier; groups diverge after this

    // ---- one-time anti-phase stagger for group 1: ~500-cyc dependent chain.
    // After this, group 1 trails group 0 by ~half a step; named barriers
    // never re-converge the groups, so the offset persists for all 512 steps.
    if (gid == 1) {
        float d = (float)(lane + 2);
#pragma unroll 4
        for (int i = 0; i < 124; i++) d = fmaf(d, 0.999f, 0.125f);
        if (d == 3.14159f) buf[1][0][0][SEGF] = d;   // never true; defeats DCE
    }

    int p = 0;
    for (int t = 0; t < TSTEPS; t++) {
        float4 xn;
        if (loader) {
            const int tn = (t + 1 < TSTEPS) ? t + 1 : TSTEPS - 1;
            xn = *(const float4*)(xrow + (size_t)tn * IDIM + c4);
        }

        const float* base = &buf[gid][p][0][0];

        // ---- pair A (stage-1 survivor): keep + shfl(send), no selects
        float ra[4];
        {
            float aK[4], aS[4];
            row_acc(base + oKA, w, aK);
            row_acc(base + oSA, w, aS);
#pragma unroll
            for (int c = 0; c < 4; c++)
                ra[c] = aK[c] + __shfl_xor_sync(0xffffffffu, aS[c], 4);
        }
        // ---- pair B
        float rb[4];
        {
            float aK[4], aS[4];
            row_acc(base + oKB, w, aK);
            row_acc(base + oSB, w, aS);
#pragma unroll
            for (int c = 0; c < 4; c++)
                rb[c] = aK[c] + __shfl_xor_sync(0xffffffffu, aS[c], 4);
        }

        // ---- stage 1 (xor 8): rows 2 -> 1
        float rc[4];
#pragma unroll
        for (int c = 0; c < 4; c++)
            rc[c] = ra[c] + __shfl_xor_sync(0xffffffffu, rb[c], 8);

        // ---- stage 2 (xor 16): cols 4 -> 2 (order pre-permuted via cg)
        const float f0 = rc[0] + __shfl_xor_sync(0xffffffffu, rc[2], 16);
        const float f1 = rc[1] + __shfl_xor_sync(0xffffffffu, rc[3], 16);

        // ---- publish h_t: row mstar, cols of0, of1
        const int q = p ^ 1;
        buf[gid][q][mstar][ph0] = tanh_fast(f0 + bb0);
        buf[gid][q][mstar][ph1] = tanh_fast(f1 + bb1);

        if (loader) *(float4*)&buf[gid][q][xr][pc4] = xn;

        group_bar(gid);    // ONLY this group's 256 threads
        p = q;
    }

    // ---- final projection (group-local; reads only this group's buf)
    if (tg < ROWS * ODIM) {
        const int m = tg / ODIM;
        const int j = tg % ODIM;
        float s = b_ph[j];
#pragma unroll 4
        for (int k = 0; k < HDIM; k++)
            s += buf[gid][p][m][physk(IDIM + k)] * W_ph[j * HDIM + k];
        out[(size_t)(b0r + m) * ODIM + j] = s;
    }
}

extern "C" void kernel_launch(void* const* d_in, const int* in_sizes, int n_in,
                              void* d_out, int out_size) {
    const float* x    = (const float*)d_in[0];
    const float* W_hx = (const float*)d_in[1];
    const float* W_hh = (const float*)d_in[2];
    const float* b_hh = (const float*)d_in[3];
    const float* W_ph = (const float*)d_in[4];
    const float* b_ph = (const float*)d_in[5];
    float* out = (float*)d_out;

    rnn_fused_kernel<<<GRID, NTHREADS>>>(x, W_hx, W_hh, b_hh, W_ph, b_ph, out);
}